// round 14
// baseline (speedup 1.0000x reference)
#include <cuda_runtime.h>
#include <cuda_fp16.h>
#include <math.h>
#include <stdint.h>

#define BATCH 8
#define CH 64
#define CP 32              // channel pairs
#define HH 512
#define WW 512
#define LL (HH*WW)
#define DSTATE 16
#define CUT 2048
#define BN_EPS 1e-5f

// scratch: xp/xc as packed fp16 channel pairs (u32 = {ch 2c, ch 2c+1})
__device__ unsigned g_xph[(size_t)BATCH*CP*LL];
__device__ unsigned g_xch[(size_t)BATCH*CP*LL];
__device__ float g_Bp[BATCH*DSTATE*CUT];
__device__ float g_Sp[BATCH*DSTATE*CUT];
__device__ float g_S [BATCH*DSTATE];

// pre-swizzled fp16 weight tiles
__device__ __align__(16) unsigned char g_Win[8192];
__device__ __align__(16) unsigned char g_Wg [16384];
__device__ __align__(16) unsigned char g_Wo [8192];

// single-MUFU tanh (sm_75+)
__device__ __forceinline__ float tanhap(float x){
  float y; asm("tanh.approx.f32 %0, %1;" : "=f"(y) : "f"(x)); return y;
}
__device__ __forceinline__ float fsig(float x){
  return fmaf(tanhap(0.5f*x), 0.5f, 0.5f);
}
__device__ __forceinline__ float fsilu(float x){
  return x * fsig(x);
}

#define SW128(o) ((o) ^ (((o)>>3)&0x70))

__device__ __forceinline__ uint32_t smem_u32(const void* p){
  uint32_t a;
  asm("{ .reg .u64 t; cvta.to.shared.u64 t, %1; cvt.u32.u64 %0, t; }"
      : "=r"(a) : "l"(p));
  return a;
}
__device__ __forceinline__ void ldsm4(unsigned r[4], uint32_t a){
  asm volatile("ldmatrix.sync.aligned.m8n8.x4.shared.b16 {%0,%1,%2,%3}, [%4];"
    : "=r"(r[0]),"=r"(r[1]),"=r"(r[2]),"=r"(r[3]) : "r"(a));
}
__device__ __forceinline__ void ldsm2(unsigned r[2], uint32_t a){
  asm volatile("ldmatrix.sync.aligned.m8n8.x2.shared.b16 {%0,%1}, [%2];"
    : "=r"(r[0]),"=r"(r[1]) : "r"(a));
}
__device__ __forceinline__ void mmah(float d[4], const unsigned a[4], const unsigned b0, const unsigned b1){
  asm volatile("mma.sync.aligned.m16n8k16.row.col.f32.f16.f16.f32 "
    "{%0,%1,%2,%3}, {%4,%5,%6,%7}, {%8,%9}, {%0,%1,%2,%3};"
    : "+f"(d[0]),"+f"(d[1]),"+f"(d[2]),"+f"(d[3])
    : "r"(a[0]),"r"(a[1]),"r"(a[2]),"r"(a[3]), "r"(b0),"r"(b1));
}
__device__ __forceinline__ void unpackh2(unsigned u, float& a, float& b){
  __half2 h = *(__half2*)&u;
  a = __half2float(__low2half(h));
  b = __half2float(__high2half(h));
}
__device__ __forceinline__ unsigned packh2(float a, float b){
  __half2 h = __floats2half2_rn(a, b);
  return *(unsigned*)&h;
}

// ---------------------------------------------------------------------------
// K0a/b/c: one-time weight prep (fp16, SW128-swizzled 128B rows), split into
// 3 launches so k_inproj sits at profile launch index 3.
// ---------------------------------------------------------------------------
__global__ void k_prep_win(const float* __restrict__ w_in){
  const int tid = threadIdx.x;
  for (int idx=tid; idx<4096; idx+=256){
    int n = idx>>6, k = idx&63;
    unsigned off = SW128((unsigned)(n*128 + k*2));
    *(__half*)(g_Win+off) = __float2half_rn(w_in[idx]);
  }
}
__global__ void k_prep_wg(const float* __restrict__ wg){
  const int tid = threadIdx.x;
  for (int idx=tid; idx<8192; idx+=256){
    int n = idx>>6, k = idx&63;
    unsigned off = SW128((unsigned)(n*128 + k*2));
    *(__half*)(g_Wg+off) = __float2half_rn(wg[idx]);
  }
}
__global__ void k_prep_wo(const float* __restrict__ wo){
  const int tid = threadIdx.x;
  for (int idx=tid; idx<4096; idx+=256){
    int n = idx>>6, k = idx&63;
    unsigned off = SW128((unsigned)(n*128 + k*2));
    *(__half*)(g_Wo+off) = __float2half_rn(wo[idx]);
  }
}

// ---------------------------------------------------------------------------
// K1: xp = silu(bn(w_in @ x)) — fp16 1-pass mma. 256 px/block, 256 thr.
// ---------------------------------------------------------------------------
__global__ __launch_bounds__(256,2) void k_inproj(
    const float* __restrict__ x,
    const float* __restrict__ gin, const float* __restrict__ bin)
{
  extern __shared__ char dynraw[];
  char* base = (char*)(((uintptr_t)dynraw + 1023) & ~(uintptr_t)1023);
  char* Ah = base;            // 32KB
  char* Wt = base + 32768;    // 8KB
  __shared__ float sg[64], sb[64];

  const int tid = threadIdx.x, lane = tid&31, warp = tid>>5;
  const int b = blockIdx.y;
  const long p0 = (long)blockIdx.x*256;

  for (int idx=tid; idx<512; idx+=256)
    ((uint4*)Wt)[idx] = ((const uint4*)g_Win)[idx];
  if (tid<64){ sg[tid]=gin[tid]*rsqrtf(1.f+BN_EPS); sb[tid]=bin[tid]; }

  { // A staging: thread = pixel, single fp16 pass
    const float* xb = x + (long)b*CH*LL + p0 + tid;
    #pragma unroll
    for (int kb=0;kb<8;kb++){
      unsigned h[4];
      #pragma unroll
      for (int j=0;j<4;j++)
        h[j] = packh2(xb[(long)(8*kb+2*j)*LL], xb[(long)(8*kb+2*j+1)*LL]);
      unsigned off = SW128((unsigned)(tid*128 + kb*16));
      *(uint4*)(Ah+off) = make_uint4(h[0],h[1],h[2],h[3]);
    }
  }
  __syncthreads();

  const uint32_t AhB=smem_u32(Ah), WtB=smem_u32(Wt);
  float acc[2][8][4];
  #pragma unroll
  for (int mt=0;mt<2;mt++)
    #pragma unroll
    for (int nt=0;nt<8;nt++)
      #pragma unroll
      for (int r=0;r<4;r++) acc[mt][nt][r]=0.f;

  const int Mb = warp*32;
  const int arow = (lane&7) + ((lane>>3)&1)*8;
  const int achk = lane>>4;
  const int brow = lane&7;
  const int bchk = (lane>>3)&1;

  #pragma unroll
  for (int ks=0; ks<4; ks++){
    unsigned ah[2][4];
    #pragma unroll
    for (int mt=0; mt<2; mt++){
      unsigned off = SW128((unsigned)((Mb+16*mt+arow)*128 + (2*ks+achk)*16));
      ldsm4(ah[mt], AhB+off);
    }
    #pragma unroll
    for (int nt=0; nt<8; nt++){
      unsigned boff = SW128((unsigned)((8*nt+brow)*128 + (2*ks+bchk)*16));
      unsigned bw[2];
      ldsm2(bw, WtB+boff);
      #pragma unroll
      for (int mt=0;mt<2;mt++)
        mmah(acc[mt][nt], ah[mt], bw[0], bw[1]);
    }
  }

  // direct paired epilogue: BN + SiLU + half2 store
  unsigned* dst = g_xph + (size_t)b*CP*LL + p0;
  #pragma unroll
  for (int mt=0;mt<2;mt++){
    const int m = Mb + 16*mt + (lane>>2);
    #pragma unroll
    for (int nt=0;nt<8;nt++){
      const int n = 8*nt + 2*(lane&3);
      const size_t rowoff = (size_t)(n>>1)*LL;
      float s0 = sg[n], b0 = sb[n], s1 = sg[n+1], b1 = sb[n+1];
      float v0 = fsilu(fmaf(acc[mt][nt][0], s0, b0));
      float v1 = fsilu(fmaf(acc[mt][nt][1], s1, b1));
      float v2 = fsilu(fmaf(acc[mt][nt][2], s0, b0));
      float v3 = fsilu(fmaf(acc[mt][nt][3], s1, b1));
      dst[rowoff + m]     = packh2(v0, v1);
      dst[rowoff + m + 8] = packh2(v2, v3);
    }
  }
}

// ---------------------------------------------------------------------------
// K2: depthwise 3x3 + BN + SiLU, channel pair per block, half2 data.
// ---------------------------------------------------------------------------
__global__ __launch_bounds__(128) void k_dwconv(
    const float* __restrict__ wdw, const float* __restrict__ gcv,
    const float* __restrict__ bcv)
{
  __shared__ unsigned s[18*512];   // 36 KB, half2 per px
  const int tid = threadIdx.x;
  const int b = blockIdx.z, c2 = blockIdx.y, h0 = blockIdx.x*16;
  const unsigned* src = g_xph + (size_t)(b*CP+c2)*LL;

  #pragma unroll
  for (int r=0;r<18;r++){
    int hh = h0 - 1 + r;
    uint4 v = make_uint4(0u,0u,0u,0u);
    if (hh >= 0 && hh < HH) v = *(const uint4*)(src + (long)hh*WW + (tid<<2));
    *(uint4*)(s + r*512 + (tid<<2)) = v;
  }
  __syncthreads();

  const int c0 = 2*c2, c1 = c0+1;
  float ka[9], kb[9];
  #pragma unroll
  for (int i=0;i<9;i++){ ka[i]=wdw[c0*9+i]; kb[i]=wdw[c1*9+i]; }
  const float rs = rsqrtf(1.0f+BN_EPS);
  const float sc0 = gcv[c0]*rs, be0 = bcv[c0];
  const float sc1 = gcv[c1]*rs, be1 = bcv[c1];
  const int w = tid<<2;
  unsigned* dst = g_xch + (size_t)(b*CP+c2)*LL + (long)h0*WW + w;

  for (int r=0;r<16;r++){
    float a0[3][6], a1[3][6];
    #pragma unroll
    for (int dy=0;dy<3;dy++){
      const unsigned* row = s + (r+dy)*512;
      unsigned e0 = (w>0)? row[w-1] : 0u;
      uint4 m = *(const uint4*)(row + w);
      unsigned e5 = (w<508)? row[w+4] : 0u;
      unpackh2(e0,  a0[dy][0], a1[dy][0]);
      unpackh2(m.x, a0[dy][1], a1[dy][1]);
      unpackh2(m.y, a0[dy][2], a1[dy][2]);
      unpackh2(m.z, a0[dy][3], a1[dy][3]);
      unpackh2(m.w, a0[dy][4], a1[dy][4]);
      unpackh2(e5,  a0[dy][5], a1[dy][5]);
    }
    unsigned o[4];
    #pragma unroll
    for (int j=0;j<4;j++){
      float u = ka[0]*a0[0][j] + ka[1]*a0[0][j+1] + ka[2]*a0[0][j+2]
              + ka[3]*a0[1][j] + ka[4]*a0[1][j+1] + ka[5]*a0[1][j+2]
              + ka[6]*a0[2][j] + ka[7]*a0[2][j+1] + ka[8]*a0[2][j+2];
      float v = kb[0]*a1[0][j] + kb[1]*a1[0][j+1] + kb[2]*a1[0][j+2]
              + kb[3]*a1[1][j] + kb[4]*a1[1][j+1] + kb[5]*a1[1][j+2]
              + kb[6]*a1[2][j] + kb[7]*a1[2][j+1] + kb[8]*a1[2][j+2];
      u = fsilu(fmaf(u, sc0, be0));
      v = fsilu(fmaf(v, sc1, be1));
      o[j] = packh2(u, v);
    }
    *(uint4*)(dst + (long)r*WW) = make_uint4(o[0],o[1],o[2],o[3]);
  }
}

// ---------------------------------------------------------------------------
// K3a: Bp = wB @ xc for k < CUT (paired xc reads)
// ---------------------------------------------------------------------------
__global__ __launch_bounds__(256) void k_bproj(const float* __restrict__ wB)
{
  __shared__ float swB[DSTATE*64];
  __shared__ float red[256][17];
  const int tid = threadIdx.x;
  const int b = blockIdx.y;
  const int px = tid & 63, cg = tid >> 6;
  const int k = blockIdx.x*64 + px;

  for (int idx=tid; idx<DSTATE*64; idx+=256) swB[idx] = wB[idx];
  __syncthreads();

  const unsigned* xcb = g_xch + (size_t)b*CP*LL + k;
  float acc[16];
  #pragma unroll
  for (int s=0;s<16;s++) acc[s]=0.f;
  #pragma unroll
  for (int i=0;i<8;i++){
    int cp = cg*8 + i;
    float xv0, xv1;
    unpackh2(xcb[(size_t)cp*LL], xv0, xv1);
    #pragma unroll
    for (int s=0;s<16;s++){
      acc[s] = fmaf(swB[s*64+2*cp],   xv0, acc[s]);
      acc[s] = fmaf(swB[s*64+2*cp+1], xv1, acc[s]);
    }
  }
  #pragma unroll
  for (int s=0;s<16;s++) red[tid][s] = acc[s];
  __syncthreads();
  if (cg == 0){
    #pragma unroll
    for (int s=0;s<16;s++){
      float v = red[px][s] + red[64+px][s] + red[128+px][s] + red[192+px][s];
      g_Bp[(b*DSTATE+s)*CUT + k] = v;
    }
  }
}

__global__ __launch_bounds__(256) void k_scan(const float* __restrict__ A)
{
  __shared__ float t[CUT];
  const int bs = blockIdx.x;
  const int s = bs & 15;
  const float a = A[s];
  for (int idx = threadIdx.x; idx < CUT; idx += 256)
    t[idx] = g_Bp[bs*CUT + idx] * expf(a * (float)idx);
  __syncthreads();
  if (threadIdx.x == 0){
    float acc = 0.f;
    for (int k=0;k<CUT;k++){ acc += t[k]; t[k] = acc; }
    g_S[bs] = acc;
  }
  __syncthreads();
  for (int idx = threadIdx.x; idx < CUT; idx += 256)
    g_Sp[bs*CUT + idx] = t[idx];
}

// ---------------------------------------------------------------------------
// K4: gate GEMM (1-pass) + combine + out GEMM (1-pass).
// 128 px/block, 256 thr, 3 blocks/SM. Combine accumulates directly into
// out-GEMM A-fragment registers (no xg smem round trip).
// ---------------------------------------------------------------------------
__global__ __launch_bounds__(256,3) void k_final(
  const float* __restrict__ wC, const float* __restrict__ Dv,
  const float* __restrict__ gg, const float* __restrict__ bg,
  const float* __restrict__ go, const float* __restrict__ bo,
  float* __restrict__ out)
{
  extern __shared__ char dynraw[];
  char* base = (char*)(((uintptr_t)dynraw + 1023) & ~(uintptr_t)1023);
  char* Ah = base;            // 16KB (xp)
  char* Wg = base + 16384;    // 16KB
  char* Wo = base + 32768;    // 8KB   (total 40KB)
  __shared__ float s_gsc[128], s_gbe[128], s_dvec[64], s_cvec[64], s_osc[64], s_obe[64];
  __shared__ float s_wC[64*16];

  const int tid = threadIdx.x, lane = tid&31, warp = tid>>5;
  const int b = blockIdx.y;
  const long p0 = (long)blockIdx.x*128;
  const bool boundary = (p0 < CUT);
  const float rs = rsqrtf(1.0f+BN_EPS);

  for (int idx=tid; idx<1024; idx+=256)
    ((uint4*)Wg)[idx] = ((const uint4*)g_Wg)[idx];
  for (int idx=tid; idx<512; idx+=256)
    ((uint4*)Wo)[idx] = ((const uint4*)g_Wo)[idx];
  if (tid < 128){ s_gsc[tid] = gg[tid]*rs; s_gbe[tid] = bg[tid]; }
  for (int idx=tid; idx<1024; idx+=256) s_wC[idx] = wC[idx];
  if (tid < 64){
    s_dvec[tid] = Dv[tid];
    s_osc[tid]  = go[tid]*rs;
    s_obe[tid]  = bo[tid];
    float c = 0.f;
    #pragma unroll
    for (int s=0;s<16;s++) c = fmaf(wC[tid*16+s], g_S[b*16+s], c);
    s_cvec[tid] = c;
  }

  { // A staging from packed fp16 xp: plain u32 gathers
    const int px = tid & 127, half = tid >> 7;
    const unsigned* xpb = g_xph + (size_t)b*CP*LL + p0 + px;
    #pragma unroll
    for (int j=0;j<4;j++){
      const int cp0 = half*16 + j*4;
      uint4 v;
      v.x = xpb[(size_t)(cp0+0)*LL];
      v.y = xpb[(size_t)(cp0+1)*LL];
      v.z = xpb[(size_t)(cp0+2)*LL];
      v.w = xpb[(size_t)(cp0+3)*LL];
      unsigned off = SW128((unsigned)(px*128 + (half*4+j)*16));
      *(uint4*)(Ah+off) = v;
    }
  }
  __syncthreads();

  const uint32_t AhB=smem_u32(Ah), WgB=smem_u32(Wg), WoB=smem_u32(Wo);
  const int Mb = warp*16;
  const int arow = (lane&7) + ((lane>>3)&1)*8;
  const int achk = lane>>4;
  const int brow = lane&7;
  const int bchk = (lane>>3)&1;

  // preload A fragments (xp, exact fp16): 16 regs
  unsigned ah[4][4];
  #pragma unroll
  for (int ks=0; ks<4; ks++){
    unsigned aoff = SW128((unsigned)((Mb+arow)*128 + (2*ks+achk)*16));
    ldsm4(ah[ks], AhB+aoff);
  }

  // out-GEMM A fragments, filled directly by combine
  unsigned aout[4][4];

  // gate GEMM (1-pass) + combine, streamed per nt
  const unsigned* xcb = g_xch + (size_t)b*CP*LL + p0;
  #pragma unroll
  for (int nt=0; nt<8; nt++){
    float accg[4] = {0.f,0.f,0.f,0.f};
    float accs[4] = {0.f,0.f,0.f,0.f};
    #pragma unroll
    for (int ks=0; ks<4; ks++){
      unsigned bgo = SW128((unsigned)((8*nt+brow)*128 + (2*ks+bchk)*16));
      unsigned bso = SW128((unsigned)((8*(nt+8)+brow)*128 + (2*ks+bchk)*16));
      unsigned bw[2];
      ldsm2(bw, WgB+bgo);
      mmah(accg, ah[ks], bw[0], bw[1]);
      ldsm2(bw, WgB+bso);
      mmah(accs, ah[ks], bw[0], bw[1]);
    }
    const int ch0 = 8*nt + 2*(lane&3), ch1 = ch0+1;
    const float dv0 = s_dvec[ch0], dv1 = s_dvec[ch1];
    const size_t xrow = (size_t)(ch0>>1)*LL;
    #pragma unroll
    for (int rp=0; rp<2; rp++){
      const int pxl = Mb + (lane>>2) + rp*8;
      float base0, base1;
      if (boundary){
        const long p = p0 + pxl;
        float d0=0.f, d1=0.f;
        for (int s=0;s<16;s++){
          float sv = g_Sp[(b*DSTATE+s)*CUT + p];
          d0 = fmaf(s_wC[ch0*16+s], sv, d0);
          d1 = fmaf(s_wC[ch1*16+s], sv, d1);
        }
        base0=d0; base1=d1;
      } else { base0 = s_cvec[ch0]; base1 = s_cvec[ch1]; }
      float xc0, xc1;
      unpackh2(xcb[xrow + pxl], xc0, xc1);
      float g0 = fmaf(accg[2*rp],   s_gsc[ch0], s_gbe[ch0]);
      float g1 = fmaf(accg[2*rp+1], s_gsc[ch1], s_gbe[ch1]);
      float h0 = fmaf(accs[2*rp],   s_gsc[64+ch0], s_gbe[64+ch0]);
      float h1 = fmaf(accs[2*rp+1], s_gsc[64+ch1], s_gbe[64+ch1]);
      float v0 = fsig(g0)*(fmaf(dv0, xc0, base0) + tanhap(h0));
      float v1 = fsig(g1)*(fmaf(dv1, xc1, base1) + tanhap(h1));
      // gate C-fragment == out A-fragment a[(nt&1)*2+rp] of k-chunk nt>>1
      aout[nt>>1][((nt&1)<<1) + rp] = packh2(v0, v1);
    }
  }

  // out GEMM (1-pass) straight from registers
  float acc2[8][4];
  #pragma unroll
  for (int nt=0;nt<8;nt++)
    #pragma unroll
    for (int r=0;r<4;r++) acc2[nt][r]=0.f;
  #pragma unroll
  for (int ks=0; ks<4; ks++){
    #pragma unroll
    for (int nt=0; nt<8; nt++){
      unsigned boff = SW128((unsigned)((8*nt+brow)*128 + (2*ks+bchk)*16));
      unsigned bw[2];
      ldsm2(bw, WoB+boff);
      mmah(acc2[nt], aout[ks], bw[0], bw[1]);
    }
  }

  // direct fp32 epilogue
  float* dst = out + (long)b*CH*LL + p0;
  const int m = Mb + (lane>>2);
  #pragma unroll
  for (int nt=0;nt<8;nt++){
    const int n = 8*nt + 2*(lane&3);
    float s0 = s_osc[n], b0 = s_obe[n], s1 = s_osc[n+1], b1 = s_obe[n+1];
    dst[(long)n*LL + m]         = fmaf(acc2[nt][0], s0, b0);
    dst[(long)(n+1)*LL + m]     = fmaf(acc2[nt][1], s1, b1);
    dst[(long)n*LL + m + 8]     = fmaf(acc2[nt][2], s0, b0);
    dst[(long)(n+1)*LL + m + 8] = fmaf(acc2[nt][3], s1, b1);
  }
}

// ---------------------------------------------------------------------------
extern "C" void kernel_launch(void* const* d_in, const int* in_sizes, int n_in,
                              void* d_out, int out_size)
{
  const float* x    = (const float*)d_in[0];
  const float* w_in = (const float*)d_in[1];
  const float* gin  = (const float*)d_in[2];
  const float* bin  = (const float*)d_in[3];
  const float* wdw  = (const float*)d_in[4];
  const float* gcv  = (const float*)d_in[5];
  const float* bcv  = (const float*)d_in[6];
  const float* wB   = (const float*)d_in[7];
  const float* wC   = (const float*)d_in[8];
  const float* A    = (const float*)d_in[9];
  const float* Dv   = (const float*)d_in[10];
  const float* wg   = (const float*)d_in[11];
  const float* gg   = (const float*)d_in[12];
  const float* bg   = (const float*)d_in[13];
  const float* wo   = (const float*)d_in[14];
  const float* go   = (const float*)d_in[15];
  const float* bo   = (const float*)d_in[16];
  float* out = (float*)d_out;

  const int SM1 = 40960 + 1024;
  const int SM4 = 40960 + 1024;
  cudaFuncSetAttribute(k_inproj, cudaFuncAttributeMaxDynamicSharedMemorySize, SM1);
  cudaFuncSetAttribute(k_final,  cudaFuncAttributeMaxDynamicSharedMemorySize, SM4);

  k_prep_win<<<1, 256>>>(w_in);
  k_prep_wg <<<1, 256>>>(wg);
  k_prep_wo <<<1, 256>>>(wo);
  k_inproj<<<dim3(LL/256, BATCH), 256, SM1>>>(x, gin, bin);
  k_dwconv<<<dim3(HH/16, CP, BATCH), 128>>>(wdw, gcv, bcv);
  k_bproj <<<dim3(CUT/64, BATCH), 256>>>(wB);
  k_scan  <<<BATCH*DSTATE, 256>>>(A);
  k_final <<<dim3(LL/128, BATCH), 256, SM4>>>(wC, Dv, gg, bg, go, bo, out);
}

// round 15
// speedup vs baseline: 1.3410x; 1.3410x over previous
#include <cuda_runtime.h>
#include <cuda_fp16.h>
#include <math.h>
#include <stdint.h>

#define BATCH 8
#define CH 64
#define CP 32              // channel pairs
#define HH 512
#define WW 512
#define LL (HH*WW)
#define DSTATE 16
#define CUT 2048
#define BN_EPS 1e-5f

// scratch: xp/xc as packed fp16 channel pairs (u32 = {ch 2c, ch 2c+1})
__device__ unsigned g_xph[(size_t)BATCH*CP*LL];
__device__ unsigned g_xch[(size_t)BATCH*CP*LL];
__device__ float g_Bp[BATCH*DSTATE*CUT];
__device__ float g_Sp[BATCH*DSTATE*CUT];
__device__ float g_S [BATCH*DSTATE];

// pre-swizzled fp16 weight tiles
__device__ __align__(16) unsigned char g_Win[8192];
__device__ __align__(16) unsigned char g_Wg [16384];
__device__ __align__(16) unsigned char g_Wo [8192];

__device__ __forceinline__ float fsig(float x){
  return __fdividef(1.0f, 1.0f + __expf(-x));
}
__device__ __forceinline__ float ftanh(float x){
  x = fminf(fmaxf(x, -15.f), 15.f);
  float e = __expf(2.f*x);
  return __fdividef(e-1.f, e+1.f);
}

#define SW128(o) ((o) ^ (((o)>>3)&0x70))

__device__ __forceinline__ uint32_t smem_u32(const void* p){
  uint32_t a;
  asm("{ .reg .u64 t; cvta.to.shared.u64 t, %1; cvt.u32.u64 %0, t; }"
      : "=r"(a) : "l"(p));
  return a;
}
__device__ __forceinline__ void ldsm4(unsigned r[4], uint32_t a){
  asm volatile("ldmatrix.sync.aligned.m8n8.x4.shared.b16 {%0,%1,%2,%3}, [%4];"
    : "=r"(r[0]),"=r"(r[1]),"=r"(r[2]),"=r"(r[3]) : "r"(a));
}
__device__ __forceinline__ void ldsm2(unsigned r[2], uint32_t a){
  asm volatile("ldmatrix.sync.aligned.m8n8.x2.shared.b16 {%0,%1}, [%2];"
    : "=r"(r[0]),"=r"(r[1]) : "r"(a));
}
__device__ __forceinline__ void mmah(float d[4], const unsigned a[4], const unsigned b0, const unsigned b1){
  asm volatile("mma.sync.aligned.m16n8k16.row.col.f32.f16.f16.f32 "
    "{%0,%1,%2,%3}, {%4,%5,%6,%7}, {%8,%9}, {%0,%1,%2,%3};"
    : "+f"(d[0]),"+f"(d[1]),"+f"(d[2]),"+f"(d[3])
    : "r"(a[0]),"r"(a[1]),"r"(a[2]),"r"(a[3]), "r"(b0),"r"(b1));
}
__device__ __forceinline__ void unpackh2(unsigned u, float& a, float& b){
  __half2 h = *(__half2*)&u;
  a = __half2float(__low2half(h));
  b = __half2float(__high2half(h));
}
__device__ __forceinline__ unsigned packh2(float a, float b){
  __half2 h = __floats2half2_rn(a, b);
  return *(unsigned*)&h;
}

// ---------------------------------------------------------------------------
// K0: one-time weight prep (fp16, SW128-swizzled 128B rows)
// ---------------------------------------------------------------------------
__global__ void k_prep(const float* __restrict__ w_in,
                       const float* __restrict__ wg,
                       const float* __restrict__ wo)
{
  const int tid = threadIdx.x;
  for (int idx=tid; idx<4096; idx+=256){
    int n = idx>>6, k = idx&63;
    unsigned off = SW128((unsigned)(n*128 + k*2));
    *(__half*)(g_Win+off) = __float2half_rn(w_in[idx]);
    *(__half*)(g_Wo +off) = __float2half_rn(wo[idx]);
  }
  for (int idx=tid; idx<8192; idx+=256){
    int n = idx>>6, k = idx&63;
    unsigned off = SW128((unsigned)(n*128 + k*2));
    *(__half*)(g_Wg+off) = __float2half_rn(wg[idx]);
  }
}

// ---------------------------------------------------------------------------
// K1: xp = silu(bn(w_in @ x)) — fp16 1-pass mma.
// 128 px/block, 256 thr, m16/warp, 3 blocks/SM for DRAM BW.
// ---------------------------------------------------------------------------
__global__ __launch_bounds__(256,3) void k_inproj(
    const float* __restrict__ x,
    const float* __restrict__ gin, const float* __restrict__ bin)
{
  extern __shared__ char dynraw[];
  char* base = (char*)(((uintptr_t)dynraw + 1023) & ~(uintptr_t)1023);
  char* Ah = base;            // 16KB
  char* Wt = base + 16384;    // 8KB  (total 24KB)
  __shared__ float sg[64], sb[64];

  const int tid = threadIdx.x, lane = tid&31, warp = tid>>5;
  const int b = blockIdx.y;
  const long p0 = (long)blockIdx.x*128;

  for (int idx=tid; idx<512; idx+=256)
    ((uint4*)Wt)[idx] = ((const uint4*)g_Win)[idx];
  if (tid<64){ sg[tid]=gin[tid]*rsqrtf(1.f+BN_EPS); sb[tid]=bin[tid]; }

  { // A staging: px = tid&127, channel half = tid>>7 (16 ch each)
    const int px = tid & 127, half = tid >> 7;
    const float* xb = x + (long)b*CH*LL + (long)(half*32)*LL + p0 + px;
    #pragma unroll
    for (int j=0;j<4;j++){
      unsigned h[4];
      #pragma unroll
      for (int c=0;c<4;c++)
        h[c] = packh2(xb[(long)(8*j+2*c)*LL], xb[(long)(8*j+2*c+1)*LL]);
      unsigned off = SW128((unsigned)(px*128 + (half*4+j)*16));
      *(uint4*)(Ah+off) = make_uint4(h[0],h[1],h[2],h[3]);
    }
  }
  __syncthreads();

  const uint32_t AhB=smem_u32(Ah), WtB=smem_u32(Wt);
  float acc[8][4];
  #pragma unroll
  for (int nt=0;nt<8;nt++)
    #pragma unroll
    for (int r=0;r<4;r++) acc[nt][r]=0.f;

  const int Mb = warp*16;
  const int arow = (lane&7) + ((lane>>3)&1)*8;
  const int achk = lane>>4;
  const int brow = lane&7;
  const int bchk = (lane>>3)&1;

  unsigned ah[4][4];
  #pragma unroll
  for (int ks=0; ks<4; ks++){
    unsigned aoff = SW128((unsigned)((Mb+arow)*128 + (2*ks+achk)*16));
    ldsm4(ah[ks], AhB+aoff);
  }
  #pragma unroll
  for (int ks=0; ks<4; ks++){
    #pragma unroll
    for (int nt=0; nt<8; nt++){
      unsigned boff = SW128((unsigned)((8*nt+brow)*128 + (2*ks+bchk)*16));
      unsigned bw[2];
      ldsm2(bw, WtB+boff);
      mmah(acc[nt], ah[ks], bw[0], bw[1]);
    }
  }

  // direct paired epilogue: BN + SiLU + half2 store
  unsigned* dst = g_xph + (size_t)b*CP*LL + p0;
  const int m = Mb + (lane>>2);
  #pragma unroll
  for (int nt=0;nt<8;nt++){
    const int n = 8*nt + 2*(lane&3);
    const size_t rowoff = (size_t)(n>>1)*LL;
    float s0 = sg[n], b0 = sb[n], s1 = sg[n+1], b1 = sb[n+1];
    float v0 = fmaf(acc[nt][0], s0, b0); v0 *= fsig(v0);
    float v1 = fmaf(acc[nt][1], s1, b1); v1 *= fsig(v1);
    float v2 = fmaf(acc[nt][2], s0, b0); v2 *= fsig(v2);
    float v3 = fmaf(acc[nt][3], s1, b1); v3 *= fsig(v3);
    dst[rowoff + m]     = packh2(v0, v1);
    dst[rowoff + m + 8] = packh2(v2, v3);
  }
}

// ---------------------------------------------------------------------------
// K2: depthwise 3x3 + BN + SiLU, channel pair per block, half2 data.
// ---------------------------------------------------------------------------
__global__ __launch_bounds__(128) void k_dwconv(
    const float* __restrict__ wdw, const float* __restrict__ gcv,
    const float* __restrict__ bcv)
{
  __shared__ unsigned s[18*512];   // 36 KB, half2 per px
  const int tid = threadIdx.x;
  const int b = blockIdx.z, c2 = blockIdx.y, h0 = blockIdx.x*16;
  const unsigned* src = g_xph + (size_t)(b*CP+c2)*LL;

  #pragma unroll
  for (int r=0;r<18;r++){
    int hh = h0 - 1 + r;
    uint4 v = make_uint4(0u,0u,0u,0u);
    if (hh >= 0 && hh < HH) v = *(const uint4*)(src + (long)hh*WW + (tid<<2));
    *(uint4*)(s + r*512 + (tid<<2)) = v;
  }
  __syncthreads();

  const int c0 = 2*c2, c1 = c0+1;
  float ka[9], kb[9];
  #pragma unroll
  for (int i=0;i<9;i++){ ka[i]=wdw[c0*9+i]; kb[i]=wdw[c1*9+i]; }
  const float rs = rsqrtf(1.0f+BN_EPS);
  const float sc0 = gcv[c0]*rs, be0 = bcv[c0];
  const float sc1 = gcv[c1]*rs, be1 = bcv[c1];
  const int w = tid<<2;
  unsigned* dst = g_xch + (size_t)(b*CP+c2)*LL + (long)h0*WW + w;

  for (int r=0;r<16;r++){
    float a0[3][6], a1[3][6];
    #pragma unroll
    for (int dy=0;dy<3;dy++){
      const unsigned* row = s + (r+dy)*512;
      unsigned e0 = (w>0)? row[w-1] : 0u;
      uint4 m = *(const uint4*)(row + w);
      unsigned e5 = (w<508)? row[w+4] : 0u;
      unpackh2(e0,  a0[dy][0], a1[dy][0]);
      unpackh2(m.x, a0[dy][1], a1[dy][1]);
      unpackh2(m.y, a0[dy][2], a1[dy][2]);
      unpackh2(m.z, a0[dy][3], a1[dy][3]);
      unpackh2(m.w, a0[dy][4], a1[dy][4]);
      unpackh2(e5,  a0[dy][5], a1[dy][5]);
    }
    unsigned o[4];
    #pragma unroll
    for (int j=0;j<4;j++){
      float u = ka[0]*a0[0][j] + ka[1]*a0[0][j+1] + ka[2]*a0[0][j+2]
              + ka[3]*a0[1][j] + ka[4]*a0[1][j+1] + ka[5]*a0[1][j+2]
              + ka[6]*a0[2][j] + ka[7]*a0[2][j+1] + ka[8]*a0[2][j+2];
      float v = kb[0]*a1[0][j] + kb[1]*a1[0][j+1] + kb[2]*a1[0][j+2]
              + kb[3]*a1[1][j] + kb[4]*a1[1][j+1] + kb[5]*a1[1][j+2]
              + kb[6]*a1[2][j] + kb[7]*a1[2][j+1] + kb[8]*a1[2][j+2];
      u = fmaf(u, sc0, be0); u *= fsig(u);
      v = fmaf(v, sc1, be1); v *= fsig(v);
      o[j] = packh2(u, v);
    }
    *(uint4*)(dst + (long)r*WW) = make_uint4(o[0],o[1],o[2],o[3]);
  }
}

// ---------------------------------------------------------------------------
// K3a: Bp = wB @ xc for k < CUT (paired xc reads)
// ---------------------------------------------------------------------------
__global__ __launch_bounds__(256) void k_bproj(const float* __restrict__ wB)
{
  __shared__ float swB[DSTATE*64];
  __shared__ float red[256][17];
  const int tid = threadIdx.x;
  const int b = blockIdx.y;
  const int px = tid & 63, cg = tid >> 6;
  const int k = blockIdx.x*64 + px;

  for (int idx=tid; idx<DSTATE*64; idx+=256) swB[idx] = wB[idx];
  __syncthreads();

  const unsigned* xcb = g_xch + (size_t)b*CP*LL + k;
  float acc[16];
  #pragma unroll
  for (int s=0;s<16;s++) acc[s]=0.f;
  #pragma unroll
  for (int i=0;i<8;i++){
    int cp = cg*8 + i;
    float xv0, xv1;
    unpackh2(xcb[(size_t)cp*LL], xv0, xv1);
    #pragma unroll
    for (int s=0;s<16;s++){
      acc[s] = fmaf(swB[s*64+2*cp],   xv0, acc[s]);
      acc[s] = fmaf(swB[s*64+2*cp+1], xv1, acc[s]);
    }
  }
  #pragma unroll
  for (int s=0;s<16;s++) red[tid][s] = acc[s];
  __syncthreads();
  if (cg == 0){
    #pragma unroll
    for (int s=0;s<16;s++){
      float v = red[px][s] + red[64+px][s] + red[128+px][s] + red[192+px][s];
      g_Bp[(b*DSTATE+s)*CUT + k] = v;
    }
  }
}

__global__ __launch_bounds__(256) void k_scan(const float* __restrict__ A)
{
  __shared__ float t[CUT];
  const int bs = blockIdx.x;
  const int s = bs & 15;
  const float a = A[s];
  for (int idx = threadIdx.x; idx < CUT; idx += 256)
    t[idx] = g_Bp[bs*CUT + idx] * expf(a * (float)idx);
  __syncthreads();
  if (threadIdx.x == 0){
    float acc = 0.f;
    for (int k=0;k<CUT;k++){ acc += t[k]; t[k] = acc; }
    g_S[bs] = acc;
  }
  __syncthreads();
  for (int idx = threadIdx.x; idx < CUT; idx += 256)
    g_Sp[bs*CUT + idx] = t[idx];
}

// ---------------------------------------------------------------------------
// K4: gate GEMM (1-pass) + combine + out GEMM (1-pass).
// 128 px/block, 256 thr, 3 blocks/SM. Combine accumulates directly into
// out-GEMM A-fragment registers (no xg smem round trip).
// ---------------------------------------------------------------------------
__global__ __launch_bounds__(256,3) void k_final(
  const float* __restrict__ wC, const float* __restrict__ Dv,
  const float* __restrict__ gg, const float* __restrict__ bg,
  const float* __restrict__ go, const float* __restrict__ bo,
  float* __restrict__ out)
{
  extern __shared__ char dynraw[];
  char* base = (char*)(((uintptr_t)dynraw + 1023) & ~(uintptr_t)1023);
  char* Ah = base;            // 16KB (xp)
  char* Wg = base + 16384;    // 16KB
  char* Wo = base + 32768;    // 8KB   (total 40KB)
  __shared__ float s_gsc[128], s_gbe[128], s_dvec[64], s_cvec[64], s_osc[64], s_obe[64];
  __shared__ float s_wC[64*16];

  const int tid = threadIdx.x, lane = tid&31, warp = tid>>5;
  const int b = blockIdx.y;
  const long p0 = (long)blockIdx.x*128;
  const bool boundary = (p0 < CUT);
  const float rs = rsqrtf(1.0f+BN_EPS);

  for (int idx=tid; idx<1024; idx+=256)
    ((uint4*)Wg)[idx] = ((const uint4*)g_Wg)[idx];
  for (int idx=tid; idx<512; idx+=256)
    ((uint4*)Wo)[idx] = ((const uint4*)g_Wo)[idx];
  if (tid < 128){ s_gsc[tid] = gg[tid]*rs; s_gbe[tid] = bg[tid]; }
  for (int idx=tid; idx<1024; idx+=256) s_wC[idx] = wC[idx];
  if (tid < 64){
    s_dvec[tid] = Dv[tid];
    s_osc[tid]  = go[tid]*rs;
    s_obe[tid]  = bo[tid];
    float c = 0.f;
    #pragma unroll
    for (int s=0;s<16;s++) c = fmaf(wC[tid*16+s], g_S[b*16+s], c);
    s_cvec[tid] = c;
  }

  { // A staging from packed fp16 xp: plain u32 gathers
    const int px = tid & 127, half = tid >> 7;
    const unsigned* xpb = g_xph + (size_t)b*CP*LL + p0 + px;
    #pragma unroll
    for (int j=0;j<4;j++){
      const int cp0 = half*16 + j*4;
      uint4 v;
      v.x = xpb[(size_t)(cp0+0)*LL];
      v.y = xpb[(size_t)(cp0+1)*LL];
      v.z = xpb[(size_t)(cp0+2)*LL];
      v.w = xpb[(size_t)(cp0+3)*LL];
      unsigned off = SW128((unsigned)(px*128 + (half*4+j)*16));
      *(uint4*)(Ah+off) = v;
    }
  }
  __syncthreads();

  const uint32_t AhB=smem_u32(Ah), WgB=smem_u32(Wg), WoB=smem_u32(Wo);
  const int Mb = warp*16;
  const int arow = (lane&7) + ((lane>>3)&1)*8;
  const int achk = lane>>4;
  const int brow = lane&7;
  const int bchk = (lane>>3)&1;

  // preload A fragments (xp, exact fp16): 16 regs
  unsigned ah[4][4];
  #pragma unroll
  for (int ks=0; ks<4; ks++){
    unsigned aoff = SW128((unsigned)((Mb+arow)*128 + (2*ks+achk)*16));
    ldsm4(ah[ks], AhB+aoff);
  }

  // out-GEMM A fragments, filled directly by combine
  unsigned aout[4][4];

  // gate GEMM (1-pass) + combine, streamed per nt
  const unsigned* xcb = g_xch + (size_t)b*CP*LL + p0;
  #pragma unroll
  for (int nt=0; nt<8; nt++){
    float accg[4] = {0.f,0.f,0.f,0.f};
    float accs[4] = {0.f,0.f,0.f,0.f};
    #pragma unroll
    for (int ks=0; ks<4; ks++){
      unsigned bgo = SW128((unsigned)((8*nt+brow)*128 + (2*ks+bchk)*16));
      unsigned bso = SW128((unsigned)((8*(nt+8)+brow)*128 + (2*ks+bchk)*16));
      unsigned bw[2];
      ldsm2(bw, WgB+bgo);
      mmah(accg, ah[ks], bw[0], bw[1]);
      ldsm2(bw, WgB+bso);
      mmah(accs, ah[ks], bw[0], bw[1]);
    }
    const int ch0 = 8*nt + 2*(lane&3), ch1 = ch0+1;
    const float dv0 = s_dvec[ch0], dv1 = s_dvec[ch1];
    const size_t xrow = (size_t)(ch0>>1)*LL;
    #pragma unroll
    for (int rp=0; rp<2; rp++){
      const int pxl = Mb + (lane>>2) + rp*8;
      float base0, base1;
      if (boundary){
        const long p = p0 + pxl;
        float d0=0.f, d1=0.f;
        for (int s=0;s<16;s++){
          float sv = g_Sp[(b*DSTATE+s)*CUT + p];
          d0 = fmaf(s_wC[ch0*16+s], sv, d0);
          d1 = fmaf(s_wC[ch1*16+s], sv, d1);
        }
        base0=d0; base1=d1;
      } else { base0 = s_cvec[ch0]; base1 = s_cvec[ch1]; }
      float xc0, xc1;
      unpackh2(xcb[xrow + pxl], xc0, xc1);
      float g0 = fmaf(accg[2*rp],   s_gsc[ch0], s_gbe[ch0]);
      float g1 = fmaf(accg[2*rp+1], s_gsc[ch1], s_gbe[ch1]);
      float h0 = fmaf(accs[2*rp],   s_gsc[64+ch0], s_gbe[64+ch0]);
      float h1 = fmaf(accs[2*rp+1], s_gsc[64+ch1], s_gbe[64+ch1]);
      float v0 = fsig(g0)*(fmaf(dv0, xc0, base0) + ftanh(h0));
      float v1 = fsig(g1)*(fmaf(dv1, xc1, base1) + ftanh(h1));
      // gate C-fragment == out A-fragment a[(nt&1)*2+rp] of k-chunk nt>>1
      aout[nt>>1][((nt&1)<<1) + rp] = packh2(v0, v1);
    }
  }

  // out GEMM (1-pass) straight from registers
  float acc2[8][4];
  #pragma unroll
  for (int nt=0;nt<8;nt++)
    #pragma unroll
    for (int r=0;r<4;r++) acc2[nt][r]=0.f;
  #pragma unroll
  for (int ks=0; ks<4; ks++){
    #pragma unroll
    for (int nt=0; nt<8; nt++){
      unsigned boff = SW128((unsigned)((8*nt+brow)*128 + (2*ks+bchk)*16));
      unsigned bw[2];
      ldsm2(bw, WoB+boff);
      mmah(acc2[nt], aout[ks], bw[0], bw[1]);
    }
  }

  // direct fp32 epilogue
  float* dst = out + (long)b*CH*LL + p0;
  const int m = Mb + (lane>>2);
  #pragma unroll
  for (int nt=0;nt<8;nt++){
    const int n = 8*nt + 2*(lane&3);
    float s0 = s_osc[n], b0 = s_obe[n], s1 = s_osc[n+1], b1 = s_obe[n+1];
    dst[(long)n*LL + m]         = fmaf(acc2[nt][0], s0, b0);
    dst[(long)(n+1)*LL + m]     = fmaf(acc2[nt][1], s1, b1);
    dst[(long)n*LL + m + 8]     = fmaf(acc2[nt][2], s0, b0);
    dst[(long)(n+1)*LL + m + 8] = fmaf(acc2[nt][3], s1, b1);
  }
}

// ---------------------------------------------------------------------------
extern "C" void kernel_launch(void* const* d_in, const int* in_sizes, int n_in,
                              void* d_out, int out_size)
{
  const float* x    = (const float*)d_in[0];
  const float* w_in = (const float*)d_in[1];
  const float* gin  = (const float*)d_in[2];
  const float* bin  = (const float*)d_in[3];
  const float* wdw  = (const float*)d_in[4];
  const float* gcv  = (const float*)d_in[5];
  const float* bcv  = (const float*)d_in[6];
  const float* wB   = (const float*)d_in[7];
  const float* wC   = (const float*)d_in[8];
  const float* A    = (const float*)d_in[9];
  const float* Dv   = (const float*)d_in[10];
  const float* wg   = (const float*)d_in[11];
  const float* gg   = (const float*)d_in[12];
  const float* bg   = (const float*)d_in[13];
  const float* wo   = (const float*)d_in[14];
  const float* go   = (const float*)d_in[15];
  const float* bo   = (const float*)d_in[16];
  float* out = (float*)d_out;

  const int SM1 = 24576 + 1024;
  const int SM4 = 40960 + 1024;
  cudaFuncSetAttribute(k_inproj, cudaFuncAttributeMaxDynamicSharedMemorySize, SM1);
  cudaFuncSetAttribute(k_final,  cudaFuncAttributeMaxDynamicSharedMemorySize, SM4);

  k_prep  <<<1, 256>>>(w_in, wg, wo);
  k_inproj<<<dim3(LL/128, BATCH), 256, SM1>>>(x, gin, bin);
  k_dwconv<<<dim3(HH/16, CP, BATCH), 128>>>(wdw, gcv, bcv);
  k_bproj <<<dim3(CUT/64, BATCH), 256>>>(wB);
  k_scan  <<<BATCH*DSTATE, 256>>>(A);
  k_final <<<dim3(LL/128, BATCH), 256, SM4>>>(wC, Dv, gg, bg, go, bo, out);
}

// round 16
// speedup vs baseline: 1.3450x; 1.0030x over previous
#include <cuda_runtime.h>
#include <cuda_fp16.h>
#include <math.h>
#include <stdint.h>

#define BATCH 8
#define CH 64
#define CP 32              // channel pairs
#define HH 512
#define WW 512
#define LL (HH*WW)
#define DSTATE 16
#define CUT 2048
#define BN_EPS 1e-5f

// scratch: xp/xc as packed fp16 channel pairs (u32 = {ch 2c, ch 2c+1})
__device__ unsigned g_xph[(size_t)BATCH*CP*LL];
__device__ unsigned g_xch[(size_t)BATCH*CP*LL];
__device__ float g_Bp[BATCH*DSTATE*CUT];
__device__ float g_Sp[BATCH*DSTATE*CUT];
__device__ float g_S [BATCH*DSTATE];

// pre-swizzled fp16 weight tiles
__device__ __align__(16) unsigned char g_Win[8192];
__device__ __align__(16) unsigned char g_Wg [16384];
__device__ __align__(16) unsigned char g_Wo [8192];

__device__ __forceinline__ float fsig(float x){
  return __fdividef(1.0f, 1.0f + __expf(-x));
}
__device__ __forceinline__ float ftanh(float x){
  x = fminf(fmaxf(x, -15.f), 15.f);
  float e = __expf(2.f*x);
  return __fdividef(e-1.f, e+1.f);
}

#define SW128(o) ((o) ^ (((o)>>3)&0x70))

__device__ __forceinline__ uint32_t smem_u32(const void* p){
  uint32_t a;
  asm("{ .reg .u64 t; cvta.to.shared.u64 t, %1; cvt.u32.u64 %0, t; }"
      : "=r"(a) : "l"(p));
  return a;
}
__device__ __forceinline__ void ldsm4(unsigned r[4], uint32_t a){
  asm volatile("ldmatrix.sync.aligned.m8n8.x4.shared.b16 {%0,%1,%2,%3}, [%4];"
    : "=r"(r[0]),"=r"(r[1]),"=r"(r[2]),"=r"(r[3]) : "r"(a));
}
__device__ __forceinline__ void ldsm2(unsigned r[2], uint32_t a){
  asm volatile("ldmatrix.sync.aligned.m8n8.x2.shared.b16 {%0,%1}, [%2];"
    : "=r"(r[0]),"=r"(r[1]) : "r"(a));
}
__device__ __forceinline__ void mmah(float d[4], const unsigned a[4], const unsigned b0, const unsigned b1){
  asm volatile("mma.sync.aligned.m16n8k16.row.col.f32.f16.f16.f32 "
    "{%0,%1,%2,%3}, {%4,%5,%6,%7}, {%8,%9}, {%0,%1,%2,%3};"
    : "+f"(d[0]),"+f"(d[1]),"+f"(d[2]),"+f"(d[3])
    : "r"(a[0]),"r"(a[1]),"r"(a[2]),"r"(a[3]), "r"(b0),"r"(b1));
}
__device__ __forceinline__ void unpackh2(unsigned u, float& a, float& b){
  __half2 h = *(__half2*)&u;
  a = __half2float(__low2half(h));
  b = __half2float(__high2half(h));
}
__device__ __forceinline__ unsigned packh2(float a, float b){
  __half2 h = __floats2half2_rn(a, b);
  return *(unsigned*)&h;
}

// ---------------------------------------------------------------------------
// K0: one-time weight prep (fp16, SW128-swizzled 128B rows)
// ---------------------------------------------------------------------------
__global__ void k_prep(const float* __restrict__ w_in,
                       const float* __restrict__ wg,
                       const float* __restrict__ wo)
{
  const int tid = threadIdx.x;
  for (int idx=tid; idx<4096; idx+=256){
    int n = idx>>6, k = idx&63;
    unsigned off = SW128((unsigned)(n*128 + k*2));
    *(__half*)(g_Win+off) = __float2half_rn(w_in[idx]);
    *(__half*)(g_Wo +off) = __float2half_rn(wo[idx]);
  }
  for (int idx=tid; idx<8192; idx+=256){
    int n = idx>>6, k = idx&63;
    unsigned off = SW128((unsigned)(n*128 + k*2));
    *(__half*)(g_Wg+off) = __float2half_rn(wg[idx]);
  }
}

// ---------------------------------------------------------------------------
// K1: xp = silu(bn(w_in @ x)) — fp16 1-pass mma.
// 128 px/block, 256 thr, m16/warp, 3 blocks/SM. Hoisted B addresses.
// ---------------------------------------------------------------------------
__global__ __launch_bounds__(256,3) void k_inproj(
    const float* __restrict__ x,
    const float* __restrict__ gin, const float* __restrict__ bin)
{
  extern __shared__ char dynraw[];
  char* base = (char*)(((uintptr_t)dynraw + 1023) & ~(uintptr_t)1023);
  char* Ah = base;            // 16KB
  char* Wt = base + 16384;    // 8KB  (total 24KB)
  __shared__ float sg[64], sb[64];

  const int tid = threadIdx.x, lane = tid&31, warp = tid>>5;
  const int b = blockIdx.y;
  const long p0 = (long)blockIdx.x*128;

  for (int idx=tid; idx<512; idx+=256)
    ((uint4*)Wt)[idx] = ((const uint4*)g_Win)[idx];
  if (tid<64){ sg[tid]=gin[tid]*rsqrtf(1.f+BN_EPS); sb[tid]=bin[tid]; }

  { // A staging: px = tid&127, channel half = tid>>7 (16 ch each)
    const int px = tid & 127, half = tid >> 7;
    const float* xb = x + (long)b*CH*LL + (long)(half*32)*LL + p0 + px;
    #pragma unroll
    for (int j=0;j<4;j++){
      unsigned h[4];
      #pragma unroll
      for (int c=0;c<4;c++)
        h[c] = packh2(xb[(long)(8*j+2*c)*LL], xb[(long)(8*j+2*c+1)*LL]);
      unsigned off = SW128((unsigned)(px*128 + (half*4+j)*16));
      *(uint4*)(Ah+off) = make_uint4(h[0],h[1],h[2],h[3]);
    }
  }
  __syncthreads();

  const uint32_t AhB=smem_u32(Ah), WtB=smem_u32(Wt);
  float acc[8][4];
  #pragma unroll
  for (int nt=0;nt<8;nt++)
    #pragma unroll
    for (int r=0;r<4;r++) acc[nt][r]=0.f;

  const int Mb = warp*16;
  const int arow = (lane&7) + ((lane>>3)&1)*8;
  const int achk = lane>>4;
  const unsigned brow = lane&7;
  const unsigned bchk = (lane>>3)&1;

  // hoisted B base addresses: SW128(nt*1024 + brow*128 + 32ks+16bchk)
  //   = nt*1024 + brow*128 + ((32ks+16bchk) ^ (brow<<4))
  unsigned bofs[4];
  #pragma unroll
  for (int ks=0;ks<4;ks++)
    bofs[ks] = WtB + brow*128u + (((unsigned)(32*ks) + 16u*bchk) ^ (brow<<4));

  unsigned ah[4][4];
  #pragma unroll
  for (int ks=0; ks<4; ks++){
    unsigned aoff = SW128((unsigned)((Mb+arow)*128 + (2*ks+achk)*16));
    ldsm4(ah[ks], AhB+aoff);
  }
  #pragma unroll
  for (int ks=0; ks<4; ks++){
    #pragma unroll
    for (int nt=0; nt<8; nt++){
      unsigned bw[2];
      ldsm2(bw, bofs[ks] + nt*1024u);
      mmah(acc[nt], ah[ks], bw[0], bw[1]);
    }
  }

  // direct paired epilogue: BN + SiLU + half2 store
  unsigned* dst = g_xph + (size_t)b*CP*LL + p0;
  const int m = Mb + (lane>>2);
  #pragma unroll
  for (int nt=0;nt<8;nt++){
    const int n = 8*nt + 2*(lane&3);
    const size_t rowoff = (size_t)(n>>1)*LL;
    float s0 = sg[n], b0 = sb[n], s1 = sg[n+1], b1 = sb[n+1];
    float v0 = fmaf(acc[nt][0], s0, b0); v0 *= fsig(v0);
    float v1 = fmaf(acc[nt][1], s1, b1); v1 *= fsig(v1);
    float v2 = fmaf(acc[nt][2], s0, b0); v2 *= fsig(v2);
    float v3 = fmaf(acc[nt][3], s1, b1); v3 *= fsig(v3);
    dst[rowoff + m]     = packh2(v0, v1);
    dst[rowoff + m + 8] = packh2(v2, v3);
  }
}

// ---------------------------------------------------------------------------
// K2: depthwise 3x3 + BN + SiLU, channel pair per block, half2 data.
// ---------------------------------------------------------------------------
__global__ __launch_bounds__(128) void k_dwconv(
    const float* __restrict__ wdw, const float* __restrict__ gcv,
    const float* __restrict__ bcv)
{
  __shared__ unsigned s[18*512];   // 36 KB, half2 per px
  const int tid = threadIdx.x;
  const int b = blockIdx.z, c2 = blockIdx.y, h0 = blockIdx.x*16;
  const unsigned* src = g_xph + (size_t)(b*CP+c2)*LL;

  #pragma unroll
  for (int r=0;r<18;r++){
    int hh = h0 - 1 + r;
    uint4 v = make_uint4(0u,0u,0u,0u);
    if (hh >= 0 && hh < HH) v = *(const uint4*)(src + (long)hh*WW + (tid<<2));
    *(uint4*)(s + r*512 + (tid<<2)) = v;
  }
  __syncthreads();

  const int c0 = 2*c2, c1 = c0+1;
  float ka[9], kb[9];
  #pragma unroll
  for (int i=0;i<9;i++){ ka[i]=wdw[c0*9+i]; kb[i]=wdw[c1*9+i]; }
  const float rs = rsqrtf(1.0f+BN_EPS);
  const float sc0 = gcv[c0]*rs, be0 = bcv[c0];
  const float sc1 = gcv[c1]*rs, be1 = bcv[c1];
  const int w = tid<<2;
  unsigned* dst = g_xch + (size_t)(b*CP+c2)*LL + (long)h0*WW + w;

  for (int r=0;r<16;r++){
    float a0[3][6], a1[3][6];
    #pragma unroll
    for (int dy=0;dy<3;dy++){
      const unsigned* row = s + (r+dy)*512;
      unsigned e0 = (w>0)? row[w-1] : 0u;
      uint4 m = *(const uint4*)(row + w);
      unsigned e5 = (w<508)? row[w+4] : 0u;
      unpackh2(e0,  a0[dy][0], a1[dy][0]);
      unpackh2(m.x, a0[dy][1], a1[dy][1]);
      unpackh2(m.y, a0[dy][2], a1[dy][2]);
      unpackh2(m.z, a0[dy][3], a1[dy][3]);
      unpackh2(m.w, a0[dy][4], a1[dy][4]);
      unpackh2(e5,  a0[dy][5], a1[dy][5]);
    }
    unsigned o[4];
    #pragma unroll
    for (int j=0;j<4;j++){
      float u = ka[0]*a0[0][j] + ka[1]*a0[0][j+1] + ka[2]*a0[0][j+2]
              + ka[3]*a0[1][j] + ka[4]*a0[1][j+1] + ka[5]*a0[1][j+2]
              + ka[6]*a0[2][j] + ka[7]*a0[2][j+1] + ka[8]*a0[2][j+2];
      float v = kb[0]*a1[0][j] + kb[1]*a1[0][j+1] + kb[2]*a1[0][j+2]
              + kb[3]*a1[1][j] + kb[4]*a1[1][j+1] + kb[5]*a1[1][j+2]
              + kb[6]*a1[2][j] + kb[7]*a1[2][j+1] + kb[8]*a1[2][j+2];
      u = fmaf(u, sc0, be0); u *= fsig(u);
      v = fmaf(v, sc1, be1); v *= fsig(v);
      o[j] = packh2(u, v);
    }
    *(uint4*)(dst + (long)r*WW) = make_uint4(o[0],o[1],o[2],o[3]);
  }
}

// ---------------------------------------------------------------------------
// K3a: Bp = wB @ xc for k < CUT (paired xc reads)
// ---------------------------------------------------------------------------
__global__ __launch_bounds__(256) void k_bproj(const float* __restrict__ wB)
{
  __shared__ float swB[DSTATE*64];
  __shared__ float red[256][17];
  const int tid = threadIdx.x;
  const int b = blockIdx.y;
  const int px = tid & 63, cg = tid >> 6;
  const int k = blockIdx.x*64 + px;

  for (int idx=tid; idx<DSTATE*64; idx+=256) swB[idx] = wB[idx];
  __syncthreads();

  const unsigned* xcb = g_xch + (size_t)b*CP*LL + k;
  float acc[16];
  #pragma unroll
  for (int s=0;s<16;s++) acc[s]=0.f;
  #pragma unroll
  for (int i=0;i<8;i++){
    int cp = cg*8 + i;
    float xv0, xv1;
    unpackh2(xcb[(size_t)cp*LL], xv0, xv1);
    #pragma unroll
    for (int s=0;s<16;s++){
      acc[s] = fmaf(swB[s*64+2*cp],   xv0, acc[s]);
      acc[s] = fmaf(swB[s*64+2*cp+1], xv1, acc[s]);
    }
  }
  #pragma unroll
  for (int s=0;s<16;s++) red[tid][s] = acc[s];
  __syncthreads();
  if (cg == 0){
    #pragma unroll
    for (int s=0;s<16;s++){
      float v = red[px][s] + red[64+px][s] + red[128+px][s] + red[192+px][s];
      g_Bp[(b*DSTATE+s)*CUT + k] = v;
    }
  }
}

__global__ __launch_bounds__(256) void k_scan(const float* __restrict__ A)
{
  __shared__ float t[CUT];
  const int bs = blockIdx.x;
  const int s = bs & 15;
  const float a = A[s];
  for (int idx = threadIdx.x; idx < CUT; idx += 256)
    t[idx] = g_Bp[bs*CUT + idx] * expf(a * (float)idx);
  __syncthreads();
  if (threadIdx.x == 0){
    float acc = 0.f;
    for (int k=0;k<CUT;k++){ acc += t[k]; t[k] = acc; }
    g_S[bs] = acc;
  }
  __syncthreads();
  for (int idx = threadIdx.x; idx < CUT; idx += 256)
    g_Sp[bs*CUT + idx] = t[idx];
}

// ---------------------------------------------------------------------------
// K4: gate GEMM (1-pass) + combine + out GEMM (1-pass).
// 128 px/block, 256 thr, 3 blocks/SM. Combine accumulates directly into
// out-GEMM A-fragment registers. Hoisted B addresses (Wo = Wg + 16KB).
// ---------------------------------------------------------------------------
__global__ __launch_bounds__(256,3) void k_final(
  const float* __restrict__ wC, const float* __restrict__ Dv,
  const float* __restrict__ gg, const float* __restrict__ bg,
  const float* __restrict__ go, const float* __restrict__ bo,
  float* __restrict__ out)
{
  extern __shared__ char dynraw[];
  char* base = (char*)(((uintptr_t)dynraw + 1023) & ~(uintptr_t)1023);
  char* Ah = base;            // 16KB (xp)
  char* Wg = base + 16384;    // 16KB
  char* Wo = base + 32768;    // 8KB   (total 40KB; WoB = WgB + 16384)
  __shared__ float s_gsc[128], s_gbe[128], s_dvec[64], s_cvec[64], s_osc[64], s_obe[64];
  __shared__ float s_wC[64*16];

  const int tid = threadIdx.x, lane = tid&31, warp = tid>>5;
  const int b = blockIdx.y;
  const long p0 = (long)blockIdx.x*128;
  const bool boundary = (p0 < CUT);
  const float rs = rsqrtf(1.0f+BN_EPS);

  for (int idx=tid; idx<1024; idx+=256)
    ((uint4*)Wg)[idx] = ((const uint4*)g_Wg)[idx];
  for (int idx=tid; idx<512; idx+=256)
    ((uint4*)Wo)[idx] = ((const uint4*)g_Wo)[idx];
  if (tid < 128){ s_gsc[tid] = gg[tid]*rs; s_gbe[tid] = bg[tid]; }
  for (int idx=tid; idx<1024; idx+=256) s_wC[idx] = wC[idx];
  if (tid < 64){
    s_dvec[tid] = Dv[tid];
    s_osc[tid]  = go[tid]*rs;
    s_obe[tid]  = bo[tid];
    float c = 0.f;
    #pragma unroll
    for (int s=0;s<16;s++) c = fmaf(wC[tid*16+s], g_S[b*16+s], c);
    s_cvec[tid] = c;
  }

  { // A staging from packed fp16 xp: plain u32 gathers
    const int px = tid & 127, half = tid >> 7;
    const unsigned* xpb = g_xph + (size_t)b*CP*LL + p0 + px;
    #pragma unroll
    for (int j=0;j<4;j++){
      const int cp0 = half*16 + j*4;
      uint4 v;
      v.x = xpb[(size_t)(cp0+0)*LL];
      v.y = xpb[(size_t)(cp0+1)*LL];
      v.z = xpb[(size_t)(cp0+2)*LL];
      v.w = xpb[(size_t)(cp0+3)*LL];
      unsigned off = SW128((unsigned)(px*128 + (half*4+j)*16));
      *(uint4*)(Ah+off) = v;
    }
  }
  __syncthreads();

  const uint32_t AhB=smem_u32(Ah), WgB=smem_u32(Wg);
  const int Mb = warp*16;
  const int arow = (lane&7) + ((lane>>3)&1)*8;
  const int achk = lane>>4;
  const unsigned brow = lane&7;
  const unsigned bchk = (lane>>3)&1;

  // hoisted B base addresses into Wg; Wo rows = +16384, shift rows = +8192
  unsigned gof[4];
  #pragma unroll
  for (int ks=0;ks<4;ks++)
    gof[ks] = WgB + brow*128u + (((unsigned)(32*ks) + 16u*bchk) ^ (brow<<4));

  // preload A fragments (xp, exact fp16): 16 regs
  unsigned ah[4][4];
  #pragma unroll
  for (int ks=0; ks<4; ks++){
    unsigned aoff = SW128((unsigned)((Mb+arow)*128 + (2*ks+achk)*16));
    ldsm4(ah[ks], AhB+aoff);
  }

  // out-GEMM A fragments, filled directly by combine
  unsigned aout[4][4];

  // gate GEMM (1-pass) + combine, streamed per nt
  const unsigned* xcb = g_xch + (size_t)b*CP*LL + p0;
  #pragma unroll
  for (int nt=0; nt<8; nt++){
    float accg[4] = {0.f,0.f,0.f,0.f};
    float accs[4] = {0.f,0.f,0.f,0.f};
    #pragma unroll
    for (int ks=0; ks<4; ks++){
      unsigned bw[2];
      ldsm2(bw, gof[ks] + nt*1024u);
      mmah(accg, ah[ks], bw[0], bw[1]);
      ldsm2(bw, gof[ks] + nt*1024u + 8192u);
      mmah(accs, ah[ks], bw[0], bw[1]);
    }
    const int ch0 = 8*nt + 2*(lane&3), ch1 = ch0+1;
    const float dv0 = s_dvec[ch0], dv1 = s_dvec[ch1];
    const size_t xrow = (size_t)(ch0>>1)*LL;
    #pragma unroll
    for (int rp=0; rp<2; rp++){
      const int pxl = Mb + (lane>>2) + rp*8;
      float base0, base1;
      if (boundary){
        const long p = p0 + pxl;
        float d0=0.f, d1=0.f;
        for (int s=0;s<16;s++){
          float sv = g_Sp[(b*DSTATE+s)*CUT + p];
          d0 = fmaf(s_wC[ch0*16+s], sv, d0);
          d1 = fmaf(s_wC[ch1*16+s], sv, d1);
        }
        base0=d0; base1=d1;
      } else { base0 = s_cvec[ch0]; base1 = s_cvec[ch1]; }
      float xc0, xc1;
      unpackh2(xcb[xrow + pxl], xc0, xc1);
      float g0 = fmaf(accg[2*rp],   s_gsc[ch0], s_gbe[ch0]);
      float g1 = fmaf(accg[2*rp+1], s_gsc[ch1], s_gbe[ch1]);
      float h0 = fmaf(accs[2*rp],   s_gsc[64+ch0], s_gbe[64+ch0]);
      float h1 = fmaf(accs[2*rp+1], s_gsc[64+ch1], s_gbe[64+ch1]);
      float v0 = fsig(g0)*(fmaf(dv0, xc0, base0) + ftanh(h0));
      float v1 = fsig(g1)*(fmaf(dv1, xc1, base1) + ftanh(h1));
      // gate C-fragment == out A-fragment a[(nt&1)*2+rp] of k-chunk nt>>1
      aout[nt>>1][((nt&1)<<1) + rp] = packh2(v0, v1);
    }
  }

  // out GEMM (1-pass) straight from registers (Wo = Wg + 16384)
  float acc2[8][4];
  #pragma unroll
  for (int nt=0;nt<8;nt++)
    #pragma unroll
    for (int r=0;r<4;r++) acc2[nt][r]=0.f;
  #pragma unroll
  for (int ks=0; ks<4; ks++){
    #pragma unroll
    for (int nt=0; nt<8; nt++){
      unsigned bw[2];
      ldsm2(bw, gof[ks] + nt*1024u + 16384u);
      mmah(acc2[nt], aout[ks], bw[0], bw[1]);
    }
  }

  // direct fp32 epilogue
  float* dst = out + (long)b*CH*LL + p0;
  const int m = Mb + (lane>>2);
  #pragma unroll
  for (int nt=0;nt<8;nt++){
    const int n = 8*nt + 2*(lane&3);
    float s0 = s_osc[n], b0 = s_obe[n], s1 = s_osc[n+1], b1 = s_obe[n+1];
    dst[(long)n*LL + m]         = fmaf(acc2[nt][0], s0, b0);
    dst[(long)(n+1)*LL + m]     = fmaf(acc2[nt][1], s1, b1);
    dst[(long)n*LL + m + 8]     = fmaf(acc2[nt][2], s0, b0);
    dst[(long)(n+1)*LL + m + 8] = fmaf(acc2[nt][3], s1, b1);
  }
}

// ---------------------------------------------------------------------------
extern "C" void kernel_launch(void* const* d_in, const int* in_sizes, int n_in,
                              void* d_out, int out_size)
{
  const float* x    = (const float*)d_in[0];
  const float* w_in = (const float*)d_in[1];
  const float* gin  = (const float*)d_in[2];
  const float* bin  = (const float*)d_in[3];
  const float* wdw  = (const float*)d_in[4];
  const float* gcv  = (const float*)d_in[5];
  const float* bcv  = (const float*)d_in[6];
  const float* wB   = (const float*)d_in[7];
  const float* wC   = (const float*)d_in[8];
  const float* A    = (const float*)d_in[9];
  const float* Dv   = (const float*)d_in[10];
  const float* wg   = (const float*)d_in[11];
  const float* gg   = (const float*)d_in[12];
  const float* bg   = (const float*)d_in[13];
  const float* wo   = (const float*)d_in[14];
  const float* go   = (const float*)d_in[15];
  const float* bo   = (const float*)d_in[16];
  float* out = (float*)d_out;

  const int SM1 = 24576 + 1024;
  const int SM4 = 40960 + 1024;
  cudaFuncSetAttribute(k_inproj, cudaFuncAttributeMaxDynamicSharedMemorySize, SM1);
  cudaFuncSetAttribute(k_final,  cudaFuncAttributeMaxDynamicSharedMemorySize, SM4);

  k_prep  <<<1, 256>>>(w_in, wg, wo);
  k_inproj<<<dim3(LL/128, BATCH), 256, SM1>>>(x, gin, bin);
  k_dwconv<<<dim3(HH/16, CP, BATCH), 128>>>(wdw, gcv, bcv);
  k_bproj <<<dim3(CUT/64, BATCH), 256>>>(wB);
  k_scan  <<<BATCH*DSTATE, 256>>>(A);
  k_final <<<dim3(LL/128, BATCH), 256, SM4>>>(wC, Dv, gg, bg, go, bo, out);
}

// round 17
// speedup vs baseline: 1.4338x; 1.0660x over previous
#include <cuda_runtime.h>
#include <cuda_fp16.h>
#include <math.h>
#include <stdint.h>

#define BATCH 8
#define CH 64
#define CP 32              // channel pairs
#define HH 512
#define WW 512
#define LL (HH*WW)
#define DSTATE 16
#define CUT 2048
#define BN_EPS 1e-5f

// scratch: xp/xc as packed fp16 channel pairs (u32 = {ch 2c, ch 2c+1})
__device__ unsigned g_xph[(size_t)BATCH*CP*LL];
__device__ unsigned g_xch[(size_t)BATCH*CP*LL];
__device__ float g_Bp[BATCH*DSTATE*CUT];
__device__ float g_Sp[BATCH*DSTATE*CUT];
__device__ float g_S [BATCH*DSTATE];

// pre-swizzled fp16 weight tiles
__device__ __align__(16) unsigned char g_Win[8192];
__device__ __align__(16) unsigned char g_Wg [16384];
__device__ __align__(16) unsigned char g_Wo [8192];

__device__ __forceinline__ float fsig(float x){
  return __fdividef(1.0f, 1.0f + __expf(-x));
}
__device__ __forceinline__ float ftanh(float x){
  x = fminf(fmaxf(x, -15.f), 15.f);
  float e = __expf(2.f*x);
  return __fdividef(e-1.f, e+1.f);
}

#define SW128(o) ((o) ^ (((o)>>3)&0x70))

__device__ __forceinline__ uint32_t smem_u32(const void* p){
  uint32_t a;
  asm("{ .reg .u64 t; cvta.to.shared.u64 t, %1; cvt.u32.u64 %0, t; }"
      : "=r"(a) : "l"(p));
  return a;
}
__device__ __forceinline__ void ldsm4(unsigned r[4], uint32_t a){
  asm volatile("ldmatrix.sync.aligned.m8n8.x4.shared.b16 {%0,%1,%2,%3}, [%4];"
    : "=r"(r[0]),"=r"(r[1]),"=r"(r[2]),"=r"(r[3]) : "r"(a));
}
__device__ __forceinline__ void ldsm2(unsigned r[2], uint32_t a){
  asm volatile("ldmatrix.sync.aligned.m8n8.x2.shared.b16 {%0,%1}, [%2];"
    : "=r"(r[0]),"=r"(r[1]) : "r"(a));
}
__device__ __forceinline__ void mmah(float d[4], const unsigned a[4], const unsigned b0, const unsigned b1){
  asm volatile("mma.sync.aligned.m16n8k16.row.col.f32.f16.f16.f32 "
    "{%0,%1,%2,%3}, {%4,%5,%6,%7}, {%8,%9}, {%0,%1,%2,%3};"
    : "+f"(d[0]),"+f"(d[1]),"+f"(d[2]),"+f"(d[3])
    : "r"(a[0]),"r"(a[1]),"r"(a[2]),"r"(a[3]), "r"(b0),"r"(b1));
}
__device__ __forceinline__ void unpackh2(unsigned u, float& a, float& b){
  __half2 h = *(__half2*)&u;
  a = __half2float(__low2half(h));
  b = __half2float(__high2half(h));
}
__device__ __forceinline__ unsigned packh2(float a, float b){
  __half2 h = __floats2half2_rn(a, b);
  return *(unsigned*)&h;
}

// ---------------------------------------------------------------------------
// K0: one-time weight prep (fp16, SW128-swizzled 128B rows)
// ---------------------------------------------------------------------------
__global__ void k_prep(const float* __restrict__ w_in,
                       const float* __restrict__ wg,
                       const float* __restrict__ wo)
{
  const int tid = threadIdx.x;
  for (int idx=tid; idx<4096; idx+=256){
    int n = idx>>6, k = idx&63;
    unsigned off = SW128((unsigned)(n*128 + k*2));
    *(__half*)(g_Win+off) = __float2half_rn(w_in[idx]);
    *(__half*)(g_Wo +off) = __float2half_rn(wo[idx]);
  }
  for (int idx=tid; idx<8192; idx+=256){
    int n = idx>>6, k = idx&63;
    unsigned off = SW128((unsigned)(n*128 + k*2));
    *(__half*)(g_Wg+off) = __float2half_rn(wg[idx]);
  }
}

// ---------------------------------------------------------------------------
// K1: xp = silu(bn(w_in @ x)) — fp16 1-pass mma.
// 128 px/block, 256 thr, m16/warp, 3 blocks/SM. Vectorized x staging.
// ---------------------------------------------------------------------------
__global__ __launch_bounds__(256,3) void k_inproj(
    const float* __restrict__ x,
    const float* __restrict__ gin, const float* __restrict__ bin)
{
  extern __shared__ char dynraw[];
  char* base = (char*)(((uintptr_t)dynraw + 1023) & ~(uintptr_t)1023);
  char* Ah = base;            // 16KB
  char* Wt = base + 16384;    // 8KB  (total 24KB)
  __shared__ float sg[64], sb[64];

  const int tid = threadIdx.x, lane = tid&31, warp = tid>>5;
  const int b = blockIdx.y;
  const long p0 = (long)blockIdx.x*128;

  for (int idx=tid; idx<512; idx+=256)
    ((uint4*)Wt)[idx] = ((const uint4*)g_Win)[idx];
  if (tid<64){ sg[tid]=gin[tid]*rsqrtf(1.f+BN_EPS); sb[tid]=bin[tid]; }

  { // A staging: thread = (4 px, 8 ch). 8x LDG.128, 4x STS.128
    const int px4 = (tid & 31) << 2;        // 0..124
    const int chg = tid >> 5;               // 0..7 (8 channels each)
    const float* xb = x + (long)b*CH*LL + (long)(chg*8)*LL + p0 + px4;
    uint4 u[4];
    #pragma unroll
    for (int j=0;j<4;j++){
      float4 v0 = *(const float4*)(xb + (long)(2*j)*LL);
      float4 v1 = *(const float4*)(xb + (long)(2*j+1)*LL);
      unsigned* up = (unsigned*)u;
      up[0*4+j] = packh2(v0.x, v1.x);
      up[1*4+j] = packh2(v0.y, v1.y);
      up[2*4+j] = packh2(v0.z, v1.z);
      up[3*4+j] = packh2(v0.w, v1.w);
    }
    #pragma unroll
    for (int i=0;i<4;i++){
      unsigned off = SW128((unsigned)((px4+i)*128 + chg*16));
      *(uint4*)(Ah+off) = u[i];
    }
  }
  __syncthreads();

  const uint32_t AhB=smem_u32(Ah), WtB=smem_u32(Wt);
  float acc[8][4];
  #pragma unroll
  for (int nt=0;nt<8;nt++)
    #pragma unroll
    for (int r=0;r<4;r++) acc[nt][r]=0.f;

  const int Mb = warp*16;
  const int arow = (lane&7) + ((lane>>3)&1)*8;
  const int achk = lane>>4;
  const unsigned brow = lane&7;
  const unsigned bchk = (lane>>3)&1;

  unsigned bofs[4];
  #pragma unroll
  for (int ks=0;ks<4;ks++)
    bofs[ks] = WtB + brow*128u + (((unsigned)(32*ks) + 16u*bchk) ^ (brow<<4));

  unsigned ah[4][4];
  #pragma unroll
  for (int ks=0; ks<4; ks++){
    unsigned aoff = SW128((unsigned)((Mb+arow)*128 + (2*ks+achk)*16));
    ldsm4(ah[ks], AhB+aoff);
  }
  #pragma unroll
  for (int ks=0; ks<4; ks++){
    #pragma unroll
    for (int nt=0; nt<8; nt++){
      unsigned bw[2];
      ldsm2(bw, bofs[ks] + nt*1024u);
      mmah(acc[nt], ah[ks], bw[0], bw[1]);
    }
  }

  // direct paired epilogue: BN + SiLU + half2 store
  unsigned* dst = g_xph + (size_t)b*CP*LL + p0;
  const int m = Mb + (lane>>2);
  #pragma unroll
  for (int nt=0;nt<8;nt++){
    const int n = 8*nt + 2*(lane&3);
    const size_t rowoff = (size_t)(n>>1)*LL;
    float s0 = sg[n], b0 = sb[n], s1 = sg[n+1], b1 = sb[n+1];
    float v0 = fmaf(acc[nt][0], s0, b0); v0 *= fsig(v0);
    float v1 = fmaf(acc[nt][1], s1, b1); v1 *= fsig(v1);
    float v2 = fmaf(acc[nt][2], s0, b0); v2 *= fsig(v2);
    float v3 = fmaf(acc[nt][3], s1, b1); v3 *= fsig(v3);
    dst[rowoff + m]     = packh2(v0, v1);
    dst[rowoff + m + 8] = packh2(v2, v3);
  }
}

// ---------------------------------------------------------------------------
// K2: depthwise 3x3 + BN + SiLU, channel pair per block, half2 data.
// ---------------------------------------------------------------------------
__global__ __launch_bounds__(128) void k_dwconv(
    const float* __restrict__ wdw, const float* __restrict__ gcv,
    const float* __restrict__ bcv)
{
  __shared__ unsigned s[18*512];   // 36 KB, half2 per px
  const int tid = threadIdx.x;
  const int b = blockIdx.z, c2 = blockIdx.y, h0 = blockIdx.x*16;
  const unsigned* src = g_xph + (size_t)(b*CP+c2)*LL;

  #pragma unroll
  for (int r=0;r<18;r++){
    int hh = h0 - 1 + r;
    uint4 v = make_uint4(0u,0u,0u,0u);
    if (hh >= 0 && hh < HH) v = *(const uint4*)(src + (long)hh*WW + (tid<<2));
    *(uint4*)(s + r*512 + (tid<<2)) = v;
  }
  __syncthreads();

  const int c0 = 2*c2, c1 = c0+1;
  float ka[9], kb[9];
  #pragma unroll
  for (int i=0;i<9;i++){ ka[i]=wdw[c0*9+i]; kb[i]=wdw[c1*9+i]; }
  const float rs = rsqrtf(1.0f+BN_EPS);
  const float sc0 = gcv[c0]*rs, be0 = bcv[c0];
  const float sc1 = gcv[c1]*rs, be1 = bcv[c1];
  const int w = tid<<2;
  unsigned* dst = g_xch + (size_t)(b*CP+c2)*LL + (long)h0*WW + w;

  for (int r=0;r<16;r++){
    float a0[3][6], a1[3][6];
    #pragma unroll
    for (int dy=0;dy<3;dy++){
      const unsigned* row = s + (r+dy)*512;
      unsigned e0 = (w>0)? row[w-1] : 0u;
      uint4 m = *(const uint4*)(row + w);
      unsigned e5 = (w<508)? row[w+4] : 0u;
      unpackh2(e0,  a0[dy][0], a1[dy][0]);
      unpackh2(m.x, a0[dy][1], a1[dy][1]);
      unpackh2(m.y, a0[dy][2], a1[dy][2]);
      unpackh2(m.z, a0[dy][3], a1[dy][3]);
      unpackh2(m.w, a0[dy][4], a1[dy][4]);
      unpackh2(e5,  a0[dy][5], a1[dy][5]);
    }
    unsigned o[4];
    #pragma unroll
    for (int j=0;j<4;j++){
      float u = ka[0]*a0[0][j] + ka[1]*a0[0][j+1] + ka[2]*a0[0][j+2]
              + ka[3]*a0[1][j] + ka[4]*a0[1][j+1] + ka[5]*a0[1][j+2]
              + ka[6]*a0[2][j] + ka[7]*a0[2][j+1] + ka[8]*a0[2][j+2];
      float v = kb[0]*a1[0][j] + kb[1]*a1[0][j+1] + kb[2]*a1[0][j+2]
              + kb[3]*a1[1][j] + kb[4]*a1[1][j+1] + kb[5]*a1[1][j+2]
              + kb[6]*a1[2][j] + kb[7]*a1[2][j+1] + kb[8]*a1[2][j+2];
      u = fmaf(u, sc0, be0); u *= fsig(u);
      v = fmaf(v, sc1, be1); v *= fsig(v);
      o[j] = packh2(u, v);
    }
    *(uint4*)(dst + (long)r*WW) = make_uint4(o[0],o[1],o[2],o[3]);
  }
}

// ---------------------------------------------------------------------------
// K3a: Bp = wB @ xc for k < CUT (paired xc reads)
// ---------------------------------------------------------------------------
__global__ __launch_bounds__(256) void k_bproj(const float* __restrict__ wB)
{
  __shared__ float swB[DSTATE*64];
  __shared__ float red[256][17];
  const int tid = threadIdx.x;
  const int b = blockIdx.y;
  const int px = tid & 63, cg = tid >> 6;
  const int k = blockIdx.x*64 + px;

  for (int idx=tid; idx<DSTATE*64; idx+=256) swB[idx] = wB[idx];
  __syncthreads();

  const unsigned* xcb = g_xch + (size_t)b*CP*LL + k;
  float acc[16];
  #pragma unroll
  for (int s=0;s<16;s++) acc[s]=0.f;
  #pragma unroll
  for (int i=0;i<8;i++){
    int cp = cg*8 + i;
    float xv0, xv1;
    unpackh2(xcb[(size_t)cp*LL], xv0, xv1);
    #pragma unroll
    for (int s=0;s<16;s++){
      acc[s] = fmaf(swB[s*64+2*cp],   xv0, acc[s]);
      acc[s] = fmaf(swB[s*64+2*cp+1], xv1, acc[s]);
    }
  }
  #pragma unroll
  for (int s=0;s<16;s++) red[tid][s] = acc[s];
  __syncthreads();
  if (cg == 0){
    #pragma unroll
    for (int s=0;s<16;s++){
      float v = red[px][s] + red[64+px][s] + red[128+px][s] + red[192+px][s];
      g_Bp[(b*DSTATE+s)*CUT + k] = v;
    }
  }
}

__global__ __launch_bounds__(256) void k_scan(const float* __restrict__ A)
{
  __shared__ float t[CUT];
  const int bs = blockIdx.x;
  const int s = bs & 15;
  const float a = A[s];
  for (int idx = threadIdx.x; idx < CUT; idx += 256)
    t[idx] = g_Bp[bs*CUT + idx] * expf(a * (float)idx);
  __syncthreads();
  if (threadIdx.x == 0){
    float acc = 0.f;
    for (int k=0;k<CUT;k++){ acc += t[k]; t[k] = acc; }
    g_S[bs] = acc;
  }
  __syncthreads();
  for (int idx = threadIdx.x; idx < CUT; idx += 256)
    g_Sp[bs*CUT + idx] = t[idx];
}

// ---------------------------------------------------------------------------
// K4: gate GEMM (1-pass) + combine + out GEMM (1-pass).
// 128 px/block, 256 thr, 3 blocks/SM. Combine accumulates directly into
// out-GEMM A-fragment registers. xc staged in smem (latency hiding).
// ---------------------------------------------------------------------------
__global__ __launch_bounds__(256,3) void k_final(
  const float* __restrict__ wC, const float* __restrict__ Dv,
  const float* __restrict__ gg, const float* __restrict__ bg,
  const float* __restrict__ go, const float* __restrict__ bo,
  float* __restrict__ out)
{
  extern __shared__ char dynraw[];
  char* base = (char*)(((uintptr_t)dynraw + 1023) & ~(uintptr_t)1023);
  char* Ah  = base;            // 16KB (xp)
  char* Wg  = base + 16384;    // 16KB
  char* Wo  = base + 32768;    // 8KB  (WoB = WgB + 16384)
  unsigned* xcS = (unsigned*)(base + 40960);  // [32][136] u32 = 17408B (58368 total)
  __shared__ float s_gsc[128], s_gbe[128], s_dvec[64], s_cvec[64], s_osc[64], s_obe[64];
  __shared__ float s_wC[64*16];

  const int tid = threadIdx.x, lane = tid&31, warp = tid>>5;
  const int b = blockIdx.y;
  const long p0 = (long)blockIdx.x*128;
  const bool boundary = (p0 < CUT);
  const float rs = rsqrtf(1.0f+BN_EPS);

  for (int idx=tid; idx<1024; idx+=256)
    ((uint4*)Wg)[idx] = ((const uint4*)g_Wg)[idx];
  for (int idx=tid; idx<512; idx+=256)
    ((uint4*)Wo)[idx] = ((const uint4*)g_Wo)[idx];
  if (tid < 128){ s_gsc[tid] = gg[tid]*rs; s_gbe[tid] = bg[tid]; }
  for (int idx=tid; idx<1024; idx+=256) s_wC[idx] = wC[idx];
  if (tid < 64){
    s_dvec[tid] = Dv[tid];
    s_osc[tid]  = go[tid]*rs;
    s_obe[tid]  = bo[tid];
    float c = 0.f;
    #pragma unroll
    for (int s=0;s<16;s++) c = fmaf(wC[tid*16+s], g_S[b*16+s], c);
    s_cvec[tid] = c;
  }

  { // A staging (xp) + xc staging: plain u32 gathers
    const int px = tid & 127, half = tid >> 7;
    const unsigned* xpb = g_xph + (size_t)b*CP*LL + p0 + px;
    const unsigned* xcb = g_xch + (size_t)b*CP*LL + p0 + px;
    #pragma unroll
    for (int j=0;j<4;j++){
      const int cp0 = half*16 + j*4;
      uint4 v;
      v.x = xpb[(size_t)(cp0+0)*LL];
      v.y = xpb[(size_t)(cp0+1)*LL];
      v.z = xpb[(size_t)(cp0+2)*LL];
      v.w = xpb[(size_t)(cp0+3)*LL];
      unsigned off = SW128((unsigned)(px*128 + (half*4+j)*16));
      *(uint4*)(Ah+off) = v;
      uint4 c;
      c.x = xcb[(size_t)(cp0+0)*LL];
      c.y = xcb[(size_t)(cp0+1)*LL];
      c.z = xcb[(size_t)(cp0+2)*LL];
      c.w = xcb[(size_t)(cp0+3)*LL];
      xcS[(cp0+0)*136 + px] = c.x;
      xcS[(cp0+1)*136 + px] = c.y;
      xcS[(cp0+2)*136 + px] = c.z;
      xcS[(cp0+3)*136 + px] = c.w;
    }
  }
  __syncthreads();

  const uint32_t AhB=smem_u32(Ah), WgB=smem_u32(Wg);
  const int Mb = warp*16;
  const int arow = (lane&7) + ((lane>>3)&1)*8;
  const int achk = lane>>4;
  const unsigned brow = lane&7;
  const unsigned bchk = (lane>>3)&1;

  unsigned gof[4];
  #pragma unroll
  for (int ks=0;ks<4;ks++)
    gof[ks] = WgB + brow*128u + (((unsigned)(32*ks) + 16u*bchk) ^ (brow<<4));

  // preload A fragments (xp, exact fp16): 16 regs
  unsigned ah[4][4];
  #pragma unroll
  for (int ks=0; ks<4; ks++){
    unsigned aoff = SW128((unsigned)((Mb+arow)*128 + (2*ks+achk)*16));
    ldsm4(ah[ks], AhB+aoff);
  }

  // out-GEMM A fragments, filled directly by combine
  unsigned aout[4][4];

  // gate GEMM (1-pass) + combine, streamed per nt
  #pragma unroll
  for (int nt=0; nt<8; nt++){
    float accg[4] = {0.f,0.f,0.f,0.f};
    float accs[4] = {0.f,0.f,0.f,0.f};
    #pragma unroll
    for (int ks=0; ks<4; ks++){
      unsigned bw[2];
      ldsm2(bw, gof[ks] + nt*1024u);
      mmah(accg, ah[ks], bw[0], bw[1]);
      ldsm2(bw, gof[ks] + nt*1024u + 8192u);
      mmah(accs, ah[ks], bw[0], bw[1]);
    }
    const int ch0 = 8*nt + 2*(lane&3), ch1 = ch0+1;
    const float dv0 = s_dvec[ch0], dv1 = s_dvec[ch1];
    const unsigned* xrow = xcS + (ch0>>1)*136;
    #pragma unroll
    for (int rp=0; rp<2; rp++){
      const int pxl = Mb + (lane>>2) + rp*8;
      float base0, base1;
      if (boundary){
        const long p = p0 + pxl;
        float d0=0.f, d1=0.f;
        for (int s=0;s<16;s++){
          float sv = g_Sp[(b*DSTATE+s)*CUT + p];
          d0 = fmaf(s_wC[ch0*16+s], sv, d0);
          d1 = fmaf(s_wC[ch1*16+s], sv, d1);
        }
        base0=d0; base1=d1;
      } else { base0 = s_cvec[ch0]; base1 = s_cvec[ch1]; }
      float xc0, xc1;
      unpackh2(xrow[pxl], xc0, xc1);
      float g0 = fmaf(accg[2*rp],   s_gsc[ch0], s_gbe[ch0]);
      float g1 = fmaf(accg[2*rp+1], s_gsc[ch1], s_gbe[ch1]);
      float h0 = fmaf(accs[2*rp],   s_gsc[64+ch0], s_gbe[64+ch0]);
      float h1 = fmaf(accs[2*rp+1], s_gsc[64+ch1], s_gbe[64+ch1]);
      float v0 = fsig(g0)*(fmaf(dv0, xc0, base0) + ftanh(h0));
      float v1 = fsig(g1)*(fmaf(dv1, xc1, base1) + ftanh(h1));
      // gate C-fragment == out A-fragment a[(nt&1)*2+rp] of k-chunk nt>>1
      aout[nt>>1][((nt&1)<<1) + rp] = packh2(v0, v1);
    }
  }

  // out GEMM (1-pass) straight from registers (Wo = Wg + 16384)
  float acc2[8][4];
  #pragma unroll
  for (int nt=0;nt<8;nt++)
    #pragma unroll
    for (int r=0;r<4;r++) acc2[nt][r]=0.f;
  #pragma unroll
  for (int ks=0; ks<4; ks++){
    #pragma unroll
    for (int nt=0; nt<8; nt++){
      unsigned bw[2];
      ldsm2(bw, gof[ks] + nt*1024u + 16384u);
      mmah(acc2[nt], aout[ks], bw[0], bw[1]);
    }
  }

  // direct fp32 epilogue
  float* dst = out + (long)b*CH*LL + p0;
  const int m = Mb + (lane>>2);
  #pragma unroll
  for (int nt=0;nt<8;nt++){
    const int n = 8*nt + 2*(lane&3);
    float s0 = s_osc[n], b0 = s_obe[n], s1 = s_osc[n+1], b1 = s_obe[n+1];
    dst[(long)n*LL + m]         = fmaf(acc2[nt][0], s0, b0);
    dst[(long)(n+1)*LL + m]     = fmaf(acc2[nt][1], s1, b1);
    dst[(long)n*LL + m + 8]     = fmaf(acc2[nt][2], s0, b0);
    dst[(long)(n+1)*LL + m + 8] = fmaf(acc2[nt][3], s1, b1);
  }
}

// ---------------------------------------------------------------------------
extern "C" void kernel_launch(void* const* d_in, const int* in_sizes, int n_in,
                              void* d_out, int out_size)
{
  const float* x    = (const float*)d_in[0];
  const float* w_in = (const float*)d_in[1];
  const float* gin  = (const float*)d_in[2];
  const float* bin  = (const float*)d_in[3];
  const float* wdw  = (const float*)d_in[4];
  const float* gcv  = (const float*)d_in[5];
  const float* bcv  = (const float*)d_in[6];
  const float* wB   = (const float*)d_in[7];
  const float* wC   = (const float*)d_in[8];
  const float* A    = (const float*)d_in[9];
  const float* Dv   = (const float*)d_in[10];
  const float* wg   = (const float*)d_in[11];
  const float* gg   = (const float*)d_in[12];
  const float* bg   = (const float*)d_in[13];
  const float* wo   = (const float*)d_in[14];
  const float* go   = (const float*)d_in[15];
  const float* bo   = (const float*)d_in[16];
  float* out = (float*)d_out;

  const int SM1 = 24576 + 1024;
  const int SM4 = 58368 + 1024;
  cudaFuncSetAttribute(k_inproj, cudaFuncAttributeMaxDynamicSharedMemorySize, SM1);
  cudaFuncSetAttribute(k_final,  cudaFuncAttributeMaxDynamicSharedMemorySize, SM4);

  k_prep  <<<1, 256>>>(w_in, wg, wo);
  k_inproj<<<dim3(LL/128, BATCH), 256, SM1>>>(x, gin, bin);
  k_dwconv<<<dim3(HH/16, CP, BATCH), 128>>>(wdw, gcv, bcv);
  k_bproj <<<dim3(CUT/64, BATCH), 256>>>(wB);
  k_scan  <<<BATCH*DSTATE, 256>>>(A);
  k_final <<<dim3(LL/128, BATCH), 256, SM4>>>(wC, Dv, gg, bg, go, bo, out);
}